// round 3
// baseline (speedup 1.0000x reference)
#include <cuda_runtime.h>
#include <math.h>

#define Bsz 32
#define Tlen 512
#define Hd 512

// ---------------- scratch (static device globals per harness rules) ----------
__device__ float g_xg0[(size_t)Bsz * Tlen * 4 * Hd];   // 134 MB  (dir 0 gates)
__device__ float g_xg1[(size_t)Bsz * Tlen * 4 * Hd];   // 134 MB  (dir 1 gates)
__device__ float g_x1[(size_t)Bsz * Tlen * 2 * Hd];    // 64 MB   (layer-0 output)
__device__ unsigned int g_sync[2];                     // grid barrier counters

// ---------------- SGEMM: C[M,N] = A[M,K] * W[N,K]^T + bias[N] ----------------
__global__ __launch_bounds__(256) void sgemm_bias(
    const float* __restrict__ A, const float* __restrict__ W,
    const float* __restrict__ bias, float* __restrict__ C,
    int M, int N, int K)
{
    __shared__ float As[8][128];
    __shared__ float Bs[8][128];
    const int tid = threadIdx.x;
    const int bx = blockIdx.x;   // N tile
    const int by = blockIdx.y;   // M tile

    const int lr = tid >> 1;
    const int lc = (tid & 1) << 2;
    const float* Ag = A + (size_t)(by * 128 + lr) * K + lc;
    const float* Wg = W + (size_t)(bx * 128 + lr) * K + lc;

    const int tr = (tid >> 4) << 3;
    const int tc = (tid & 15) << 3;

    float acc[8][8];
#pragma unroll
    for (int i = 0; i < 8; i++)
#pragma unroll
        for (int j = 0; j < 8; j++) acc[i][j] = 0.f;

    for (int k0 = 0; k0 < K; k0 += 8) {
        float4 av = *(const float4*)Ag;
        float4 wv = *(const float4*)Wg;
        As[lc + 0][lr] = av.x; As[lc + 1][lr] = av.y;
        As[lc + 2][lr] = av.z; As[lc + 3][lr] = av.w;
        Bs[lc + 0][lr] = wv.x; Bs[lc + 1][lr] = wv.y;
        Bs[lc + 2][lr] = wv.z; Bs[lc + 3][lr] = wv.w;
        __syncthreads();
        Ag += 8; Wg += 8;
#pragma unroll
        for (int kk = 0; kk < 8; ++kk) {
            float ar[8], br[8];
            *(float4*)&ar[0] = *(const float4*)&As[kk][tr];
            *(float4*)&ar[4] = *(const float4*)&As[kk][tr + 4];
            *(float4*)&br[0] = *(const float4*)&Bs[kk][tc];
            *(float4*)&br[4] = *(const float4*)&Bs[kk][tc + 4];
#pragma unroll
            for (int i = 0; i < 8; i++)
#pragma unroll
                for (int j = 0; j < 8; j++)
                    acc[i][j] += ar[i] * br[j];
        }
        __syncthreads();
    }

    float bv[8];
    *(float4*)&bv[0] = *(const float4*)&bias[bx * 128 + tc];
    *(float4*)&bv[4] = *(const float4*)&bias[bx * 128 + tc + 4];
#pragma unroll
    for (int i = 0; i < 8; i++) {
        float* cp = C + (size_t)(by * 128 + tr + i) * N + bx * 128 + tc;
        float4 o0, o1;
        o0.x = acc[i][0] + bv[0]; o0.y = acc[i][1] + bv[1];
        o0.z = acc[i][2] + bv[2]; o0.w = acc[i][3] + bv[3];
        o1.x = acc[i][4] + bv[4]; o1.y = acc[i][5] + bv[5];
        o1.z = acc[i][6] + bv[6]; o1.w = acc[i][7] + bv[7];
        *(float4*)cp = o0;
        *(float4*)(cp + 4) = o1;
    }
}

// ---------------- grid barrier helpers ---------------------------------------
__device__ __forceinline__ unsigned int ld_acq(const unsigned int* p) {
    unsigned int v;
    asm volatile("ld.acquire.gpu.global.u32 %0, [%1];" : "=r"(v) : "l"(p));
    return v;
}
__device__ __forceinline__ void grid_sync(unsigned int* cnt, unsigned int target) {
    __syncthreads();
    if (threadIdx.x == 0) {
        asm volatile("red.release.gpu.global.add.u32 [%0], %1;" :: "l"(cnt), "r"(1u));
        while (ld_acq(cnt) < target) { __nanosleep(64); }
    }
    __syncthreads();
}

__global__ void reset_sync(unsigned int* p) { p[0] = 0; p[1] = 0; }

// ---------------- persistent bidirectional LSTM recurrence --------------------
__device__ __forceinline__ float sigmoidf(float x) { return 1.f / (1.f + expf(-x)); }

// grid (64, 2): blockIdx.y = direction, each CTA owns 8 hidden units j for all
// 32 batch rows. 256 threads: lane = b, warp = j_local. Whh rows cached in SMEM
// once; h_{t-1} staged per step in SMEM [k][b] pitch 33; c lives in registers.
// Residency: 130 KB smem + 256 thr -> 1 CTA/SM; 128 CTAs <= 148 SMs, all wave-1
// resident, so the spin barrier cannot deadlock.
__global__ __launch_bounds__(256) void lstm_persist(
    const float* __restrict__ xg0, const float* __restrict__ xg1,
    const float* __restrict__ Whh0, const float* __restrict__ Whh1,
    float* __restrict__ seq,   // [B*T, 1024]: fwd cols 0..511, bwd 512..1023
    unsigned int* __restrict__ sync_cnt)
{
    extern __shared__ float smem[];
    float* ws = smem;                 // 16384 floats = 64 KB (weights)
    float* hs = smem + 16384;         // 512*33 floats (h staging)

    const int tid  = threadIdx.x;
    const int dir  = blockIdx.y;
    const int b    = tid & 31;
    const int warp = tid >> 5;                 // j_local 0..7
    const int jbase = blockIdx.x << 3;
    const int j    = jbase + warp;

    // Load this CTA's Whh rows into SMEM: ws row r = j_local*4 + gate (i,f,g,o)
    const float* whh = dir ? Whh1 : Whh0;
    for (int i = tid; i < 4096; i += 256) {          // float4 granules
        int r  = i >> 7;            // 0..31
        int k4 = i & 127;
        int j_local = r >> 2, gate = r & 3;
        ((float4*)ws)[r * 128 + k4] =
            ((const float4*)(whh + (size_t)(gate * 512 + jbase + j_local) * 512))[k4];
    }

    const float4* wi = (const float4*)(ws + (warp * 4 + 0) * 512);
    const float4* wf = (const float4*)(ws + (warp * 4 + 1) * 512);
    const float4* wg = (const float4*)(ws + (warp * 4 + 2) * 512);
    const float4* wo = (const float4*)(ws + (warp * 4 + 3) * 512);

    const float* xg = dir ? xg1 : xg0;
    const unsigned int nb = gridDim.x * gridDim.y;   // 128
    unsigned int target = 0;
    float c = 0.f;

    for (int s = 0; s < Tlen; ++s) {
        const int tcur = dir ? (Tlen - 1 - s) : s;

        if (s == 0) {
            for (int i = tid; i < 512 * 33; i += 256) hs[i] = 0.f;
        } else {
            const int tprev = dir ? (tcur + 1) : (tcur - 1);
            const int lb  = tid >> 3;
            const int klo = (tid & 7) << 2;
            const float* hp = seq + (size_t)(lb * Tlen + tprev) * 1024 + dir * 512;
#pragma unroll
            for (int it = 0; it < 16; ++it) {
                int k = klo + (it << 5);
                float4 v = *(const float4*)(hp + k);
                hs[(k + 0) * 33 + lb] = v.x;
                hs[(k + 1) * 33 + lb] = v.y;
                hs[(k + 2) * 33 + lb] = v.z;
                hs[(k + 3) * 33 + lb] = v.w;
            }
        }
        __syncthreads();

        float ai = 0.f, af = 0.f, ag = 0.f, ao = 0.f;
#pragma unroll 4
        for (int k4 = 0; k4 < 128; ++k4) {
            float4 vi = wi[k4], vf = wf[k4], vg = wg[k4], vo = wo[k4];
            int kb = k4 << 2;
            float h0 = hs[(kb + 0) * 33 + b];
            float h1 = hs[(kb + 1) * 33 + b];
            float h2 = hs[(kb + 2) * 33 + b];
            float h3 = hs[(kb + 3) * 33 + b];
            ai += vi.x * h0; ai += vi.y * h1; ai += vi.z * h2; ai += vi.w * h3;
            af += vf.x * h0; af += vf.y * h1; af += vf.z * h2; af += vf.w * h3;
            ag += vg.x * h0; ag += vg.y * h1; ag += vg.z * h2; ag += vg.w * h3;
            ao += vo.x * h0; ao += vo.y * h1; ao += vo.z * h2; ao += vo.w * h3;
        }

        const int base = (b * Tlen + tcur) * 2048;
        float gi = ai + xg[base + j];
        float gf = af + xg[base + 512 + j];
        float gg = ag + xg[base + 1024 + j];
        float go = ao + xg[base + 1536 + j];

        c = sigmoidf(gf) * c + sigmoidf(gi) * tanhf(gg);
        float h = sigmoidf(go) * tanhf(c);
        seq[(size_t)(b * Tlen + tcur) * 1024 + dir * 512 + j] = h;

        if (s + 1 < Tlen) {            // kernel exit is the final sync
            target += nb;
            grid_sync(sync_cnt, target);   // also guards hs overwrite next step
        }
    }
}

// ---------------- mean over T -------------------------------------------------
__global__ __launch_bounds__(256) void mean_kernel(
    const float* __restrict__ seq, float* __restrict__ avg)
{
    int idx = blockIdx.x * 256 + threadIdx.x;    // 32768 = 32 * 1024
    int b = idx >> 10;
    int n = idx & 1023;
    const float* p = seq + (size_t)b * Tlen * 1024 + n;
    float sum = 0.f;
    for (int t = 0; t < Tlen; ++t) sum += p[t * 1024];
    avg[idx] = sum * (1.f / Tlen);
}

// ---------------- launch ------------------------------------------------------
extern "C" void kernel_launch(void* const* d_in, const int* in_sizes, int n_in,
                              void* d_out, int out_size)
{
    const float* x     = (const float*)d_in[0];
    const float* Wih0f = (const float*)d_in[1];
    const float* Whh0f = (const float*)d_in[2];
    const float* b0f   = (const float*)d_in[3];
    const float* Wih0b = (const float*)d_in[4];
    const float* Whh0b = (const float*)d_in[5];
    const float* b0b   = (const float*)d_in[6];
    const float* Wih1f = (const float*)d_in[7];
    const float* Whh1f = (const float*)d_in[8];
    const float* b1f   = (const float*)d_in[9];
    const float* Wih1b = (const float*)d_in[10];
    const float* Whh1b = (const float*)d_in[11];
    const float* b1b   = (const float*)d_in[12];

    float* avg    = (float*)d_out;
    float* outseq = avg + Bsz * 2 * Hd;   // avg_out first, then out [B,T,1024]

    float *xg0, *xg1, *x1;
    unsigned int* syncp;
    cudaGetSymbolAddress((void**)&xg0, g_xg0);
    cudaGetSymbolAddress((void**)&xg1, g_xg1);
    cudaGetSymbolAddress((void**)&x1,  g_x1);
    cudaGetSymbolAddress((void**)&syncp, g_sync);

    const int smem = (16384 + 512 * 33) * sizeof(float);   // 133120 B
    cudaFuncSetAttribute(lstm_persist, cudaFuncAttributeMaxDynamicSharedMemorySize, smem);

    dim3 gemm_grid(2048 / 128, 16384 / 128);
    dim3 step_grid(64, 2);

    reset_sync<<<1, 1>>>(syncp);

    // Layer 0 input gates
    sgemm_bias<<<gemm_grid, 256>>>(x, Wih0f, b0f, xg0, 16384, 2048, 512);
    sgemm_bias<<<gemm_grid, 256>>>(x, Wih0b, b0b, xg1, 16384, 2048, 512);
    // Layer 0 recurrence (persistent, grid-sync)
    lstm_persist<<<step_grid, 256, smem>>>(xg0, xg1, Whh0f, Whh0b, x1, syncp);
    // Layer 1 input gates (K = 1024)
    sgemm_bias<<<gemm_grid, 256>>>(x1, Wih1f, b1f, xg0, 16384, 2048, 1024);
    sgemm_bias<<<gemm_grid, 256>>>(x1, Wih1b, b1b, xg1, 16384, 2048, 1024);
    // Layer 1 recurrence -> out region of d_out
    lstm_persist<<<step_grid, 256, smem>>>(xg0, xg1, Whh1f, Whh1b, outseq, syncp + 1);
    // avg_out
    mean_kernel<<<Bsz * 2 * Hd / 256, 256>>>(outseq, avg);
}

// round 4
// speedup vs baseline: 1.0755x; 1.0755x over previous
#include <cuda_runtime.h>
#include <math.h>

#define Bsz 32
#define Tlen 512
#define Hd 512

// ---------------- scratch (static device globals per harness rules) ----------
__device__ float g_xg0[(size_t)Bsz * Tlen * 4 * Hd];   // 134 MB  (dir 0 gates)
__device__ float g_xg1[(size_t)Bsz * Tlen * 4 * Hd];   // 134 MB  (dir 1 gates)
__device__ float g_x1[(size_t)Bsz * Tlen * 2 * Hd];    // 64 MB   (layer-0 output)
__device__ unsigned int g_sync[2];                     // grid barrier counters

// ---------------- tf32 helpers ------------------------------------------------
__device__ __forceinline__ float tf32_round(float v) {
    unsigned r;
    asm("cvt.rna.tf32.f32 %0, %1;" : "=r"(r) : "f"(v));
    return __uint_as_float(r);
}
__device__ __forceinline__ void mma_tf32(float* c, const unsigned* a, const unsigned* b) {
    asm volatile(
        "mma.sync.aligned.m16n8k8.row.col.f32.tf32.tf32.f32 "
        "{%0,%1,%2,%3}, {%4,%5,%6,%7}, {%8,%9}, {%0,%1,%2,%3};"
        : "+f"(c[0]), "+f"(c[1]), "+f"(c[2]), "+f"(c[3])
        : "r"(a[0]), "r"(a[1]), "r"(a[2]), "r"(a[3]), "r"(b[0]), "r"(b[1]));
}

// ---------------- TF32 split GEMM: C[M,N] = A[M,K] * W[N,K]^T + bias[N] -------
// CTA tile 128x128, k-step 16, 8 warps (2x4), warp tile 64x32.
// smem per buffer: Ahi,Alo,Bhi,Blo each [2 halves][128 rows][stride 12] floats.
#define HSTR 12
#define TILE_F (2 * 128 * HSTR)        // 3072 floats per tile-type
#define BUF_F  (4 * TILE_F)            // 12288 floats per buffer
#define GEMM_SMEM (2 * BUF_F * 4)      // 98304 bytes

__global__ __launch_bounds__(256) void tf32_gemm_bias(
    const float* __restrict__ A, const float* __restrict__ W,
    const float* __restrict__ bias, float* __restrict__ C,
    int M, int N, int K)
{
    extern __shared__ float sm[];
    const int tid  = threadIdx.x;
    const int lane = tid & 31;
    const int warp = tid >> 5;
    const int gid  = lane >> 2;        // 0..7
    const int tig  = lane & 3;         // 0..3
    const int bx = blockIdx.x, by = blockIdx.y;
    const int mo = (warp >> 2) * 64;   // warp m offset in tile
    const int no = (warp & 3) * 32;    // warp n offset in tile

    // loader mapping: q in {tid, tid+256}; row = q>>2, kq = (q&3)*4
    const int lrow = tid >> 2;         // 0..63
    const int lkq  = (tid & 3) << 2;   // 0,4,8,12
    const int lhalf = lkq >> 3;        // 0 or 1
    const int lkoff = lkq & 7;         // 0 or 4

    const float* Ag0 = A + (size_t)(by * 128 + lrow) * K + lkq;
    const float* Ag1 = A + (size_t)(by * 128 + lrow + 64) * K + lkq;
    const float* Wg0 = W + (size_t)(bx * 128 + lrow) * K + lkq;
    const float* Wg1 = W + (size_t)(bx * 128 + lrow + 64) * K + lkq;

    float c[4][4][4];
#pragma unroll
    for (int mt = 0; mt < 4; mt++)
#pragma unroll
        for (int nt = 0; nt < 4; nt++)
#pragma unroll
            for (int i = 0; i < 4; i++) c[mt][nt][i] = 0.f;

    const int nk = K >> 4;
    float4 ra0, ra1, rb0, rb1;

    // prologue: load tile 0
    ra0 = *(const float4*)Ag0; ra1 = *(const float4*)Ag1;
    rb0 = *(const float4*)Wg0; rb1 = *(const float4*)Wg1;

    auto sts_tile = [&](int p, float4 v, int region /*0=A,4=... base tile idx*/, int row) {
        float* dst_h = sm + p * BUF_F + region * TILE_F + lhalf * 1536 + row * HSTR + lkoff;
        float4 hv, lv;
        hv.x = tf32_round(v.x); lv.x = tf32_round(v.x - hv.x);
        hv.y = tf32_round(v.y); lv.y = tf32_round(v.y - hv.y);
        hv.z = tf32_round(v.z); lv.z = tf32_round(v.z - hv.z);
        hv.w = tf32_round(v.w); lv.w = tf32_round(v.w - hv.w);
        *(float4*)dst_h = hv;
        *(float4*)(dst_h + TILE_F) = lv;   // lo region sits right after hi
    };

    // regions: 0 = A hi (lo at +TILE_F), 2 = B hi (lo at +TILE_F)
    sts_tile(0, ra0, 0, lrow);
    sts_tile(0, ra1, 0, lrow + 64);
    sts_tile(0, rb0, 2, lrow);
    sts_tile(0, rb1, 2, lrow + 64);
    __syncthreads();

    int p = 0;
    for (int kt = 0; kt < nk; ++kt) {
        if (kt + 1 < nk) {
            const int k0 = (kt + 1) << 4;
            ra0 = *(const float4*)(Ag0 + k0); ra1 = *(const float4*)(Ag1 + k0);
            rb0 = *(const float4*)(Wg0 + k0); rb1 = *(const float4*)(Wg1 + k0);
        }

#pragma unroll
        for (int h = 0; h < 2; ++h) {
            const float* sA_h = sm + p * BUF_F + h * 1536;
            const float* sA_l = sA_h + TILE_F;
            const float* sB_h = sA_h + 2 * TILE_F;
            const float* sB_l = sA_h + 3 * TILE_F;

            unsigned ah[4][4], al[4][4], bh[4][2], bl[4][2];
#pragma unroll
            for (int mt = 0; mt < 4; mt++) {
                int r0 = (mo + mt * 16 + gid) * HSTR + tig;
                ah[mt][0] = __float_as_uint(sA_h[r0]);
                ah[mt][1] = __float_as_uint(sA_h[r0 + 8 * HSTR]);
                ah[mt][2] = __float_as_uint(sA_h[r0 + 4]);
                ah[mt][3] = __float_as_uint(sA_h[r0 + 8 * HSTR + 4]);
                al[mt][0] = __float_as_uint(sA_l[r0]);
                al[mt][1] = __float_as_uint(sA_l[r0 + 8 * HSTR]);
                al[mt][2] = __float_as_uint(sA_l[r0 + 4]);
                al[mt][3] = __float_as_uint(sA_l[r0 + 8 * HSTR + 4]);
            }
#pragma unroll
            for (int nt = 0; nt < 4; nt++) {
                int n0 = (no + nt * 8 + gid) * HSTR + tig;
                bh[nt][0] = __float_as_uint(sB_h[n0]);
                bh[nt][1] = __float_as_uint(sB_h[n0 + 4]);
                bl[nt][0] = __float_as_uint(sB_l[n0]);
                bl[nt][1] = __float_as_uint(sB_l[n0 + 4]);
            }
#pragma unroll
            for (int mt = 0; mt < 4; mt++)
#pragma unroll
                for (int nt = 0; nt < 4; nt++) {
                    mma_tf32(c[mt][nt], ah[mt], bh[nt]);
                    mma_tf32(c[mt][nt], ah[mt], bl[nt]);
                    mma_tf32(c[mt][nt], al[mt], bh[nt]);
                }
        }

        if (kt + 1 < nk) {
            sts_tile(1 - p, ra0, 0, lrow);
            sts_tile(1 - p, ra1, 0, lrow + 64);
            sts_tile(1 - p, rb0, 2, lrow);
            sts_tile(1 - p, rb1, 2, lrow + 64);
        }
        __syncthreads();
        p ^= 1;
    }

    // epilogue: add bias, store
#pragma unroll
    for (int nt = 0; nt < 4; nt++) {
        int col = bx * 128 + no + nt * 8 + tig * 2;
        float bv0 = bias[col], bv1 = bias[col + 1];
#pragma unroll
        for (int mt = 0; mt < 4; mt++) {
            int row0 = by * 128 + mo + mt * 16 + gid;
            float2 v0 = make_float2(c[mt][nt][0] + bv0, c[mt][nt][1] + bv1);
            float2 v1 = make_float2(c[mt][nt][2] + bv0, c[mt][nt][3] + bv1);
            *(float2*)(C + (size_t)row0 * N + col) = v0;
            *(float2*)(C + (size_t)(row0 + 8) * N + col) = v1;
        }
    }
}

// ---------------- grid barrier helpers ---------------------------------------
__device__ __forceinline__ unsigned int ld_acq(const unsigned int* p) {
    unsigned int v;
    asm volatile("ld.acquire.gpu.global.u32 %0, [%1];" : "=r"(v) : "l"(p));
    return v;
}
__device__ __forceinline__ void grid_sync(unsigned int* cnt, unsigned int target) {
    __syncthreads();
    if (threadIdx.x == 0) {
        asm volatile("red.release.gpu.global.add.u32 [%0], %1;" :: "l"(cnt), "r"(1u));
        while (ld_acq(cnt) < target) { __nanosleep(64); }
    }
    __syncthreads();
}

__global__ void reset_sync(unsigned int* p) { p[0] = 0; p[1] = 0; }

// ---------------- persistent bidirectional LSTM recurrence --------------------
__device__ __forceinline__ float sigmoidf(float x) { return 1.f / (1.f + expf(-x)); }

__global__ __launch_bounds__(256) void lstm_persist(
    const float* __restrict__ xg0, const float* __restrict__ xg1,
    const float* __restrict__ Whh0, const float* __restrict__ Whh1,
    float* __restrict__ seq,   // [B*T, 1024]: fwd cols 0..511, bwd 512..1023
    unsigned int* __restrict__ sync_cnt)
{
    extern __shared__ float smem[];
    float* ws = smem;                 // 16384 floats = 64 KB (weights)
    float* hs = smem + 16384;         // 512*33 floats (h staging)

    const int tid  = threadIdx.x;
    const int dir  = blockIdx.y;
    const int b    = tid & 31;
    const int warp = tid >> 5;
    const int jbase = blockIdx.x << 3;
    const int j    = jbase + warp;

    const float* whh = dir ? Whh1 : Whh0;
    for (int i = tid; i < 4096; i += 256) {
        int r  = i >> 7;
        int k4 = i & 127;
        int j_local = r >> 2, gate = r & 3;
        ((float4*)ws)[r * 128 + k4] =
            ((const float4*)(whh + (size_t)(gate * 512 + jbase + j_local) * 512))[k4];
    }

    const float4* wi = (const float4*)(ws + (warp * 4 + 0) * 512);
    const float4* wf = (const float4*)(ws + (warp * 4 + 1) * 512);
    const float4* wg = (const float4*)(ws + (warp * 4 + 2) * 512);
    const float4* wo = (const float4*)(ws + (warp * 4 + 3) * 512);

    const float* xg = dir ? xg1 : xg0;
    const unsigned int nb = gridDim.x * gridDim.y;   // 128
    unsigned int target = 0;
    float c = 0.f;

    for (int s = 0; s < Tlen; ++s) {
        const int tcur = dir ? (Tlen - 1 - s) : s;

        if (s == 0) {
            for (int i = tid; i < 512 * 33; i += 256) hs[i] = 0.f;
        } else {
            const int tprev = dir ? (tcur + 1) : (tcur - 1);
            const int lb  = tid >> 3;
            const int klo = (tid & 7) << 2;
            const float* hp = seq + (size_t)(lb * Tlen + tprev) * 1024 + dir * 512;
#pragma unroll
            for (int it = 0; it < 16; ++it) {
                int k = klo + (it << 5);
                float4 v = *(const float4*)(hp + k);
                hs[(k + 0) * 33 + lb] = v.x;
                hs[(k + 1) * 33 + lb] = v.y;
                hs[(k + 2) * 33 + lb] = v.z;
                hs[(k + 3) * 33 + lb] = v.w;
            }
        }
        __syncthreads();

        float ai = 0.f, af = 0.f, ag = 0.f, ao = 0.f;
#pragma unroll 4
        for (int k4 = 0; k4 < 128; ++k4) {
            float4 vi = wi[k4], vf = wf[k4], vg = wg[k4], vo = wo[k4];
            int kb = k4 << 2;
            float h0 = hs[(kb + 0) * 33 + b];
            float h1 = hs[(kb + 1) * 33 + b];
            float h2 = hs[(kb + 2) * 33 + b];
            float h3 = hs[(kb + 3) * 33 + b];
            ai += vi.x * h0; ai += vi.y * h1; ai += vi.z * h2; ai += vi.w * h3;
            af += vf.x * h0; af += vf.y * h1; af += vf.z * h2; af += vf.w * h3;
            ag += vg.x * h0; ag += vg.y * h1; ag += vg.z * h2; ag += vg.w * h3;
            ao += vo.x * h0; ao += vo.y * h1; ao += vo.z * h2; ao += vo.w * h3;
        }

        const int base = (b * Tlen + tcur) * 2048;
        float gi = ai + xg[base + j];
        float gf = af + xg[base + 512 + j];
        float gg = ag + xg[base + 1024 + j];
        float go = ao + xg[base + 1536 + j];

        c = sigmoidf(gf) * c + sigmoidf(gi) * tanhf(gg);
        float h = sigmoidf(go) * tanhf(c);
        seq[(size_t)(b * Tlen + tcur) * 1024 + dir * 512 + j] = h;

        if (s + 1 < Tlen) {
            target += nb;
            grid_sync(sync_cnt, target);
        }
    }
}

// ---------------- mean over T -------------------------------------------------
__global__ __launch_bounds__(256) void mean_kernel(
    const float* __restrict__ seq, float* __restrict__ avg)
{
    int idx = blockIdx.x * 256 + threadIdx.x;    // 32768 = 32 * 1024
    int b = idx >> 10;
    int n = idx & 1023;
    const float* p = seq + (size_t)b * Tlen * 1024 + n;
    float sum = 0.f;
    for (int t = 0; t < Tlen; ++t) sum += p[t * 1024];
    avg[idx] = sum * (1.f / Tlen);
}

// ---------------- launch ------------------------------------------------------
extern "C" void kernel_launch(void* const* d_in, const int* in_sizes, int n_in,
                              void* d_out, int out_size)
{
    const float* x     = (const float*)d_in[0];
    const float* Wih0f = (const float*)d_in[1];
    const float* Whh0f = (const float*)d_in[2];
    const float* b0f   = (const float*)d_in[3];
    const float* Wih0b = (const float*)d_in[4];
    const float* Whh0b = (const float*)d_in[5];
    const float* b0b   = (const float*)d_in[6];
    const float* Wih1f = (const float*)d_in[7];
    const float* Whh1f = (const float*)d_in[8];
    const float* b1f   = (const float*)d_in[9];
    const float* Wih1b = (const float*)d_in[10];
    const float* Whh1b = (const float*)d_in[11];
    const float* b1b   = (const float*)d_in[12];

    float* avg    = (float*)d_out;
    float* outseq = avg + Bsz * 2 * Hd;   // avg_out first, then out [B,T,1024]

    float *xg0, *xg1, *x1;
    unsigned int* syncp;
    cudaGetSymbolAddress((void**)&xg0, g_xg0);
    cudaGetSymbolAddress((void**)&xg1, g_xg1);
    cudaGetSymbolAddress((void**)&x1,  g_x1);
    cudaGetSymbolAddress((void**)&syncp, g_sync);

    const int lstm_smem = (16384 + 512 * 33) * sizeof(float);   // 133120 B
    cudaFuncSetAttribute(lstm_persist, cudaFuncAttributeMaxDynamicSharedMemorySize, lstm_smem);
    cudaFuncSetAttribute(tf32_gemm_bias, cudaFuncAttributeMaxDynamicSharedMemorySize, GEMM_SMEM);

    dim3 gemm_grid(2048 / 128, 16384 / 128);     // (16, 128)
    dim3 step_grid(64, 2);

    reset_sync<<<1, 1>>>(syncp);

    // Layer 0 input gates (tensor cores, tf32 3-term split)
    tf32_gemm_bias<<<gemm_grid, 256, GEMM_SMEM>>>(x, Wih0f, b0f, xg0, 16384, 2048, 512);
    tf32_gemm_bias<<<gemm_grid, 256, GEMM_SMEM>>>(x, Wih0b, b0b, xg1, 16384, 2048, 512);
    // Layer 0 recurrence (persistent, grid-sync)
    lstm_persist<<<step_grid, 256, lstm_smem>>>(xg0, xg1, Whh0f, Whh0b, x1, syncp);
    // Layer 1 input gates (K = 1024)
    tf32_gemm_bias<<<gemm_grid, 256, GEMM_SMEM>>>(x1, Wih1f, b1f, xg0, 16384, 2048, 1024);
    tf32_gemm_bias<<<gemm_grid, 256, GEMM_SMEM>>>(x1, Wih1b, b1b, xg1, 16384, 2048, 1024);
    // Layer 1 recurrence -> out region of d_out
    lstm_persist<<<step_grid, 256, lstm_smem>>>(xg0, xg1, Whh1f, Whh1b, outseq, syncp + 1);
    // avg_out
    mean_kernel<<<Bsz * 2 * Hd / 256, 256>>>(outseq, avg);
}

// round 7
// speedup vs baseline: 1.1734x; 1.0910x over previous
#include <cuda_runtime.h>
#include <math.h>

#define Bsz 32
#define Tlen 512
#define Hd 512

// ---------------- scratch (static device globals per harness rules) ----------
__device__ float g_xg0[(size_t)Bsz * Tlen * 4 * Hd];   // 134 MB  (dir 0 gates)
__device__ float g_xg1[(size_t)Bsz * Tlen * 4 * Hd];   // 134 MB  (dir 1 gates)
__device__ float g_x1[(size_t)Bsz * Tlen * 2 * Hd];    // 64 MB   (layer-0 output)
__device__ unsigned int g_sync[2];                     // grid barrier counters

// ---------------- tf32 helpers ------------------------------------------------
__device__ __forceinline__ float tf32_round(float v) {
    unsigned r;
    asm("cvt.rna.tf32.f32 %0, %1;" : "=r"(r) : "f"(v));
    return __uint_as_float(r);
}
__device__ __forceinline__ void mma_tf32(float* c, const unsigned* a, const unsigned* b) {
    asm volatile(
        "mma.sync.aligned.m16n8k8.row.col.f32.tf32.tf32.f32 "
        "{%0,%1,%2,%3}, {%4,%5,%6,%7}, {%8,%9}, {%0,%1,%2,%3};"
        : "+f"(c[0]), "+f"(c[1]), "+f"(c[2]), "+f"(c[3])
        : "r"(a[0]), "r"(a[1]), "r"(a[2]), "r"(a[3]), "r"(b[0]), "r"(b[1]));
}

// ---------------- TF32 split GEMM: C[M,N] = A[M,K] * W[N,K]^T + bias[N] -------
#define HSTR 12
#define TILE_F (2 * 128 * HSTR)
#define BUF_F  (4 * TILE_F)
#define GEMM_SMEM (2 * BUF_F * 4)

__global__ __launch_bounds__(256) void tf32_gemm_bias(
    const float* __restrict__ A, const float* __restrict__ W,
    const float* __restrict__ bias, float* __restrict__ C,
    int M, int N, int K)
{
    extern __shared__ float sm[];
    const int tid  = threadIdx.x;
    const int lane = tid & 31;
    const int warp = tid >> 5;
    const int gid  = lane >> 2;
    const int tig  = lane & 3;
    const int bx = blockIdx.x, by = blockIdx.y;
    const int mo = (warp >> 2) * 64;
    const int no = (warp & 3) * 32;

    const int lrow = tid >> 2;
    const int lkq  = (tid & 3) << 2;
    const int lhalf = lkq >> 3;
    const int lkoff = lkq & 7;

    const float* Ag0 = A + (size_t)(by * 128 + lrow) * K + lkq;
    const float* Ag1 = A + (size_t)(by * 128 + lrow + 64) * K + lkq;
    const float* Wg0 = W + (size_t)(bx * 128 + lrow) * K + lkq;
    const float* Wg1 = W + (size_t)(bx * 128 + lrow + 64) * K + lkq;

    float c[4][4][4];
#pragma unroll
    for (int mt = 0; mt < 4; mt++)
#pragma unroll
        for (int nt = 0; nt < 4; nt++)
#pragma unroll
            for (int i = 0; i < 4; i++) c[mt][nt][i] = 0.f;

    const int nk = K >> 4;
    float4 ra0, ra1, rb0, rb1;

    ra0 = *(const float4*)Ag0; ra1 = *(const float4*)Ag1;
    rb0 = *(const float4*)Wg0; rb1 = *(const float4*)Wg1;

    auto sts_tile = [&](int p, float4 v, int region, int row) {
        float* dst_h = sm + p * BUF_F + region * TILE_F + lhalf * 1536 + row * HSTR + lkoff;
        float4 hv, lv;
        hv.x = tf32_round(v.x); lv.x = tf32_round(v.x - hv.x);
        hv.y = tf32_round(v.y); lv.y = tf32_round(v.y - hv.y);
        hv.z = tf32_round(v.z); lv.z = tf32_round(v.z - hv.z);
        hv.w = tf32_round(v.w); lv.w = tf32_round(v.w - hv.w);
        *(float4*)dst_h = hv;
        *(float4*)(dst_h + TILE_F) = lv;
    };

    sts_tile(0, ra0, 0, lrow);
    sts_tile(0, ra1, 0, lrow + 64);
    sts_tile(0, rb0, 2, lrow);
    sts_tile(0, rb1, 2, lrow + 64);
    __syncthreads();

    int p = 0;
    for (int kt = 0; kt < nk; ++kt) {
        if (kt + 1 < nk) {
            const int k0 = (kt + 1) << 4;
            ra0 = *(const float4*)(Ag0 + k0); ra1 = *(const float4*)(Ag1 + k0);
            rb0 = *(const float4*)(Wg0 + k0); rb1 = *(const float4*)(Wg1 + k0);
        }

#pragma unroll
        for (int h = 0; h < 2; ++h) {
            const float* sA_h = sm + p * BUF_F + h * 1536;
            const float* sA_l = sA_h + TILE_F;
            const float* sB_h = sA_h + 2 * TILE_F;
            const float* sB_l = sA_h + 3 * TILE_F;

            unsigned ah[4][4], al[4][4], bh[4][2], bl[4][2];
#pragma unroll
            for (int mt = 0; mt < 4; mt++) {
                int r0 = (mo + mt * 16 + gid) * HSTR + tig;
                ah[mt][0] = __float_as_uint(sA_h[r0]);
                ah[mt][1] = __float_as_uint(sA_h[r0 + 8 * HSTR]);
                ah[mt][2] = __float_as_uint(sA_h[r0 + 4]);
                ah[mt][3] = __float_as_uint(sA_h[r0 + 8 * HSTR + 4]);
                al[mt][0] = __float_as_uint(sA_l[r0]);
                al[mt][1] = __float_as_uint(sA_l[r0 + 8 * HSTR]);
                al[mt][2] = __float_as_uint(sA_l[r0 + 4]);
                al[mt][3] = __float_as_uint(sA_l[r0 + 8 * HSTR + 4]);
            }
#pragma unroll
            for (int nt = 0; nt < 4; nt++) {
                int n0 = (no + nt * 8 + gid) * HSTR + tig;
                bh[nt][0] = __float_as_uint(sB_h[n0]);
                bh[nt][1] = __float_as_uint(sB_h[n0 + 4]);
                bl[nt][0] = __float_as_uint(sB_l[n0]);
                bl[nt][1] = __float_as_uint(sB_l[n0 + 4]);
            }
#pragma unroll
            for (int mt = 0; mt < 4; mt++)
#pragma unroll
                for (int nt = 0; nt < 4; nt++) {
                    mma_tf32(c[mt][nt], ah[mt], bh[nt]);
                    mma_tf32(c[mt][nt], ah[mt], bl[nt]);
                    mma_tf32(c[mt][nt], al[mt], bh[nt]);
                }
        }

        if (kt + 1 < nk) {
            sts_tile(1 - p, ra0, 0, lrow);
            sts_tile(1 - p, ra1, 0, lrow + 64);
            sts_tile(1 - p, rb0, 2, lrow);
            sts_tile(1 - p, rb1, 2, lrow + 64);
        }
        __syncthreads();
        p ^= 1;
    }

#pragma unroll
    for (int nt = 0; nt < 4; nt++) {
        int col = bx * 128 + no + nt * 8 + tig * 2;
        float bv0 = bias[col], bv1 = bias[col + 1];
#pragma unroll
        for (int mt = 0; mt < 4; mt++) {
            int row0 = by * 128 + mo + mt * 16 + gid;
            float2 v0 = make_float2(c[mt][nt][0] + bv0, c[mt][nt][1] + bv1);
            float2 v1 = make_float2(c[mt][nt][2] + bv0, c[mt][nt][3] + bv1);
            *(float2*)(C + (size_t)row0 * N + col) = v0;
            *(float2*)(C + (size_t)(row0 + 8) * N + col) = v1;
        }
    }
}

// ---------------- grid barrier helpers ---------------------------------------
__device__ __forceinline__ unsigned int ld_acq(const unsigned int* p) {
    unsigned int v;
    asm volatile("ld.acquire.gpu.global.u32 %0, [%1];" : "=r"(v) : "l"(p));
    return v;
}
// Bounded spin: escape after ~30M polls so a pathological stall surfaces as a
// fast wrong-answer failure instead of a container-killing hang. Never reached
// on a healthy run (waits are microseconds), so behavior is deterministic.
__device__ __forceinline__ void grid_sync(unsigned int* cnt, unsigned int target) {
    __syncthreads();
    if (threadIdx.x == 0) {
        asm volatile("red.release.gpu.global.add.u32 [%0], %1;" :: "l"(cnt), "r"(1u));
        unsigned int guard = 0;
        while (ld_acq(cnt) < target) {
            __nanosleep(64);
            if (++guard > 30000000u) break;
        }
    }
    __syncthreads();
}

__global__ void reset_sync(unsigned int* p) { p[0] = 0; p[1] = 0; }

// ---------------- persistent bidirectional LSTM recurrence --------------------
// R4 structure (known-pass): 256 threads, grid (64,2), 8 units/CTA, lane=batch,
// warp=unit. Whh in SMEM once; h staged [k][b] pitch 33 (conflict-free).
// R7 deltas: dual accumulators per gate (halved FFMA dep chains) + xg prefetch
// hoisted before the grid barrier (memory latency hidden by the spin).
__device__ __forceinline__ float sigmoidf(float x) { return 1.f / (1.f + expf(-x)); }

__global__ __launch_bounds__(256) void lstm_persist(
    const float* __restrict__ xg0, const float* __restrict__ xg1,
    const float* __restrict__ Whh0, const float* __restrict__ Whh1,
    float* __restrict__ seq,   // [B*T, 1024]: fwd cols 0..511, bwd 512..1023
    unsigned int* __restrict__ sync_cnt)
{
    extern __shared__ float smem[];
    float* ws = smem;                 // 16384 floats = 64 KB (weights)
    float* hs = smem + 16384;         // 512*33 floats (h staging)

    const int tid  = threadIdx.x;
    const int dir  = blockIdx.y;
    const int b    = tid & 31;
    const int warp = tid >> 5;
    const int jbase = blockIdx.x << 3;
    const int j    = jbase + warp;

    const float* whh = dir ? Whh1 : Whh0;
    for (int i = tid; i < 4096; i += 256) {
        int r  = i >> 7;
        int k4 = i & 127;
        int j_local = r >> 2, gate = r & 3;
        ((float4*)ws)[r * 128 + k4] =
            ((const float4*)(whh + (size_t)(gate * 512 + jbase + j_local) * 512))[k4];
    }

    const float4* wi = (const float4*)(ws + (warp * 4 + 0) * 512);
    const float4* wf = (const float4*)(ws + (warp * 4 + 1) * 512);
    const float4* wg = (const float4*)(ws + (warp * 4 + 2) * 512);
    const float4* wo = (const float4*)(ws + (warp * 4 + 3) * 512);

    const float* xg = dir ? xg1 : xg0;
    const unsigned int nb = gridDim.x * gridDim.y;   // 128
    unsigned int target = 0;
    float c = 0.f;

    // prefetch xg for step 0 (independent of h)
    float pxi, pxf, pxg, pxo;
    {
        int t0 = dir ? (Tlen - 1) : 0;
        int bs = (b * Tlen + t0) * 2048;
        pxi = xg[bs + j];        pxf = xg[bs + 512 + j];
        pxg = xg[bs + 1024 + j]; pxo = xg[bs + 1536 + j];
    }

    for (int s = 0; s < Tlen; ++s) {
        const int tcur = dir ? (Tlen - 1 - s) : s;

        if (s == 0) {
            for (int i = tid; i < 512 * 33; i += 256) hs[i] = 0.f;
        } else {
            const int tprev = dir ? (tcur + 1) : (tcur - 1);
            const int lb  = tid >> 3;
            const int klo = (tid & 7) << 2;
            const float* hp = seq + (size_t)(lb * Tlen + tprev) * 1024 + dir * 512;
#pragma unroll
            for (int it = 0; it < 16; ++it) {
                int k = klo + (it << 5);
                float4 v = *(const float4*)(hp + k);
                hs[(k + 0) * 33 + lb] = v.x;
                hs[(k + 1) * 33 + lb] = v.y;
                hs[(k + 2) * 33 + lb] = v.z;
                hs[(k + 3) * 33 + lb] = v.w;
            }
        }
        __syncthreads();

        // dual accumulators per gate: even k4 -> *, odd k4 -> *b
        float ai = 0.f, af = 0.f, ag = 0.f, ao = 0.f;
        float aib = 0.f, afb = 0.f, agb = 0.f, aob = 0.f;
#pragma unroll 2
        for (int k4 = 0; k4 < 128; k4 += 2) {
            {
                float4 vi = wi[k4], vf = wf[k4], vg = wg[k4], vo = wo[k4];
                int kb = k4 << 2;
                float h0 = hs[(kb + 0) * 33 + b];
                float h1 = hs[(kb + 1) * 33 + b];
                float h2 = hs[(kb + 2) * 33 + b];
                float h3 = hs[(kb + 3) * 33 + b];
                ai += vi.x * h0; ai += vi.y * h1; ai += vi.z * h2; ai += vi.w * h3;
                af += vf.x * h0; af += vf.y * h1; af += vf.z * h2; af += vf.w * h3;
                ag += vg.x * h0; ag += vg.y * h1; ag += vg.z * h2; ag += vg.w * h3;
                ao += vo.x * h0; ao += vo.y * h1; ao += vo.z * h2; ao += vo.w * h3;
            }
            {
                float4 vi = wi[k4 + 1], vf = wf[k4 + 1], vg = wg[k4 + 1], vo = wo[k4 + 1];
                int kb = (k4 + 1) << 2;
                float h0 = hs[(kb + 0) * 33 + b];
                float h1 = hs[(kb + 1) * 33 + b];
                float h2 = hs[(kb + 2) * 33 + b];
                float h3 = hs[(kb + 3) * 33 + b];
                aib += vi.x * h0; aib += vi.y * h1; aib += vi.z * h2; aib += vi.w * h3;
                afb += vf.x * h0; afb += vf.y * h1; afb += vf.z * h2; afb += vf.w * h3;
                agb += vg.x * h0; agb += vg.y * h1; agb += vg.z * h2; agb += vg.w * h3;
                aob += vo.x * h0; aob += vo.y * h1; aob += vo.z * h2; aob += vo.w * h3;
            }
        }

        float gi = (ai + aib) + pxi;
        float gf = (af + afb) + pxf;
        float gg = (ag + agb) + pxg;
        float go = (ao + aob) + pxo;

        c = sigmoidf(gf) * c + sigmoidf(gi) * tanhf(gg);
        float h = sigmoidf(go) * tanhf(c);
        seq[(size_t)(b * Tlen + tcur) * 1024 + dir * 512 + j] = h;

        if (s + 1 < Tlen) {
            // prefetch next step's xg before the barrier (hidden by the spin)
            int tn = dir ? (tcur - 1) : (tcur + 1);
            int bs = (b * Tlen + tn) * 2048;
            pxi = xg[bs + j];        pxf = xg[bs + 512 + j];
            pxg = xg[bs + 1024 + j]; pxo = xg[bs + 1536 + j];

            target += nb;
            grid_sync(sync_cnt, target);   // also guards hs overwrite next step
        }
    }
}

// ---------------- mean over T -------------------------------------------------
__global__ __launch_bounds__(256) void mean_kernel(
    const float* __restrict__ seq, float* __restrict__ avg)
{
    int idx = blockIdx.x * 256 + threadIdx.x;    // 32768 = 32 * 1024
    int b = idx >> 10;
    int n = idx & 1023;
    const float* p = seq + (size_t)b * Tlen * 1024 + n;
    float sum = 0.f;
    for (int t = 0; t < Tlen; ++t) sum += p[t * 1024];
    avg[idx] = sum * (1.f / Tlen);
}

// ---------------- launch ------------------------------------------------------
extern "C" void kernel_launch(void* const* d_in, const int* in_sizes, int n_in,
                              void* d_out, int out_size)
{
    const float* x     = (const float*)d_in[0];
    const float* Wih0f = (const float*)d_in[1];
    const float* Whh0f = (const float*)d_in[2];
    const float* b0f   = (const float*)d_in[3];
    const float* Wih0b = (const float*)d_in[4];
    const float* Whh0b = (const float*)d_in[5];
    const float* b0b   = (const float*)d_in[6];
    const float* Wih1f = (const float*)d_in[7];
    const float* Whh1f = (const float*)d_in[8];
    const float* b1f   = (const float*)d_in[9];
    const float* Wih1b = (const float*)d_in[10];
    const float* Whh1b = (const float*)d_in[11];
    const float* b1b   = (const float*)d_in[12];

    float* avg    = (float*)d_out;
    float* outseq = avg + Bsz * 2 * Hd;   // avg_out first, then out [B,T,1024]

    float *xg0, *xg1, *x1;
    unsigned int* syncp;
    cudaGetSymbolAddress((void**)&xg0, g_xg0);
    cudaGetSymbolAddress((void**)&xg1, g_xg1);
    cudaGetSymbolAddress((void**)&x1,  g_x1);
    cudaGetSymbolAddress((void**)&syncp, g_sync);

    const int lstm_smem = (16384 + 512 * 33) * sizeof(float);   // 133120 B
    cudaFuncSetAttribute(lstm_persist, cudaFuncAttributeMaxDynamicSharedMemorySize, lstm_smem);
    cudaFuncSetAttribute(tf32_gemm_bias, cudaFuncAttributeMaxDynamicSharedMemorySize, GEMM_SMEM);

    dim3 gemm_grid(2048 / 128, 16384 / 128);     // (16, 128)
    dim3 step_grid(64, 2);

    reset_sync<<<1, 1>>>(syncp);

    // Layer 0 input gates (tensor cores, tf32 3-term split)
    tf32_gemm_bias<<<gemm_grid, 256, GEMM_SMEM>>>(x, Wih0f, b0f, xg0, 16384, 2048, 512);
    tf32_gemm_bias<<<gemm_grid, 256, GEMM_SMEM>>>(x, Wih0b, b0b, xg1, 16384, 2048, 512);
    // Layer 0 recurrence (persistent, grid-sync)
    lstm_persist<<<step_grid, 256, lstm_smem>>>(xg0, xg1, Whh0f, Whh0b, x1, syncp);
    // Layer 1 input gates (K = 1024)
    tf32_gemm_bias<<<gemm_grid, 256, GEMM_SMEM>>>(x1, Wih1f, b1f, xg0, 16384, 2048, 1024);
    tf32_gemm_bias<<<gemm_grid, 256, GEMM_SMEM>>>(x1, Wih1b, b1b, xg1, 16384, 2048, 1024);
    // Layer 1 recurrence -> out region of d_out
    lstm_persist<<<step_grid, 256, lstm_smem>>>(xg0, xg1, Whh1f, Whh1b, outseq, syncp + 1);
    // avg_out
    mean_kernel<<<Bsz * 2 * Hd / 256, 256>>>(outseq, avg);
}

// round 9
// speedup vs baseline: 1.2925x; 1.1015x over previous
#include <cuda_runtime.h>
#include <math.h>

#define Bsz 32
#define Tlen 512
#define Hd 512

// ---------------- scratch (static device globals per harness rules) ----------
__device__ float g_xg0[(size_t)Bsz * Tlen * 4 * Hd];   // 134 MB  (dir 0 gates)
__device__ float g_xg1[(size_t)Bsz * Tlen * 4 * Hd];   // 134 MB  (dir 1 gates)
__device__ float g_x1[(size_t)Bsz * Tlen * 2 * Hd];    // 64 MB   (layer-0 output)
__device__ unsigned int g_sync[2];                     // grid barrier counters

// ---------------- tf32 helpers ------------------------------------------------
__device__ __forceinline__ float tf32_round(float v) {
    unsigned r;
    asm("cvt.rna.tf32.f32 %0, %1;" : "=r"(r) : "f"(v));
    return __uint_as_float(r);
}
__device__ __forceinline__ void mma_tf32(float* c, const unsigned* a, const unsigned* b) {
    asm volatile(
        "mma.sync.aligned.m16n8k8.row.col.f32.tf32.tf32.f32 "
        "{%0,%1,%2,%3}, {%4,%5,%6,%7}, {%8,%9}, {%0,%1,%2,%3};"
        : "+f"(c[0]), "+f"(c[1]), "+f"(c[2]), "+f"(c[3])
        : "r"(a[0]), "r"(a[1]), "r"(a[2]), "r"(a[3]), "r"(b[0]), "r"(b[1]));
}

// ---------------- TF32 2-term split GEMM: C = A*W^T + bias --------------------
// C ≈ Ahi*Whi + Ahi*Wlo  (dropped Alo*W ~ 2^-12 relative; gate is 1e-3).
// Regions per buffer: A hi (TILE_F), B hi (TILE_F), B lo (TILE_F).
#define HSTR 12
#define TILE_F (2 * 128 * HSTR)          // 3072 floats (two k-halves)
#define BUF_F  (3 * TILE_F)              // 9216 floats per buffer
#define GEMM_SMEM (2 * BUF_F * 4)        // 73728 bytes

__global__ __launch_bounds__(256) void tf32_gemm_bias(
    const float* __restrict__ A, const float* __restrict__ W,
    const float* __restrict__ bias, float* __restrict__ C,
    int M, int N, int K)
{
    extern __shared__ float sm[];
    const int tid  = threadIdx.x;
    const int lane = tid & 31;
    const int warp = tid >> 5;
    const int gid  = lane >> 2;
    const int tig  = lane & 3;
    const int bx = blockIdx.x, by = blockIdx.y;
    const int mo = (warp >> 2) * 64;
    const int no = (warp & 3) * 32;

    const int lrow = tid >> 2;
    const int lkq  = (tid & 3) << 2;
    const int lhalf = lkq >> 3;
    const int lkoff = lkq & 7;

    const float* Ag0 = A + (size_t)(by * 128 + lrow) * K + lkq;
    const float* Ag1 = A + (size_t)(by * 128 + lrow + 64) * K + lkq;
    const float* Wg0 = W + (size_t)(bx * 128 + lrow) * K + lkq;
    const float* Wg1 = W + (size_t)(bx * 128 + lrow + 64) * K + lkq;

    float c[4][4][4];
#pragma unroll
    for (int mt = 0; mt < 4; mt++)
#pragma unroll
        for (int nt = 0; nt < 4; nt++)
#pragma unroll
            for (int i = 0; i < 4; i++) c[mt][nt][i] = 0.f;

    const int nk = K >> 4;
    float4 ra0, ra1, rb0, rb1;

    ra0 = *(const float4*)Ag0; ra1 = *(const float4*)Ag1;
    rb0 = *(const float4*)Wg0; rb1 = *(const float4*)Wg1;

    // A: hi only (region 0). B: hi at TILE_F, lo at 2*TILE_F.
    auto sts_a = [&](int p, float4 v, int row) {
        float* dst = sm + p * BUF_F + lhalf * 1536 + row * HSTR + lkoff;
        float4 hv;
        hv.x = tf32_round(v.x); hv.y = tf32_round(v.y);
        hv.z = tf32_round(v.z); hv.w = tf32_round(v.w);
        *(float4*)dst = hv;
    };
    auto sts_b = [&](int p, float4 v, int row) {
        float* dst_h = sm + p * BUF_F + TILE_F + lhalf * 1536 + row * HSTR + lkoff;
        float4 hv, lv;
        hv.x = tf32_round(v.x); lv.x = tf32_round(v.x - hv.x);
        hv.y = tf32_round(v.y); lv.y = tf32_round(v.y - hv.y);
        hv.z = tf32_round(v.z); lv.z = tf32_round(v.z - hv.z);
        hv.w = tf32_round(v.w); lv.w = tf32_round(v.w - hv.w);
        *(float4*)dst_h = hv;
        *(float4*)(dst_h + TILE_F) = lv;
    };

    sts_a(0, ra0, lrow);
    sts_a(0, ra1, lrow + 64);
    sts_b(0, rb0, lrow);
    sts_b(0, rb1, lrow + 64);
    __syncthreads();

    int p = 0;
    for (int kt = 0; kt < nk; ++kt) {
        if (kt + 1 < nk) {
            const int k0 = (kt + 1) << 4;
            ra0 = *(const float4*)(Ag0 + k0); ra1 = *(const float4*)(Ag1 + k0);
            rb0 = *(const float4*)(Wg0 + k0); rb1 = *(const float4*)(Wg1 + k0);
        }

#pragma unroll
        for (int h = 0; h < 2; ++h) {
            const float* sA_h = sm + p * BUF_F + h * 1536;
            const float* sB_h = sA_h + TILE_F;
            const float* sB_l = sA_h + 2 * TILE_F;

            unsigned ah[4][4], bh[4][2], bl[4][2];
#pragma unroll
            for (int mt = 0; mt < 4; mt++) {
                int r0 = (mo + mt * 16 + gid) * HSTR + tig;
                ah[mt][0] = __float_as_uint(sA_h[r0]);
                ah[mt][1] = __float_as_uint(sA_h[r0 + 8 * HSTR]);
                ah[mt][2] = __float_as_uint(sA_h[r0 + 4]);
                ah[mt][3] = __float_as_uint(sA_h[r0 + 8 * HSTR + 4]);
            }
#pragma unroll
            for (int nt = 0; nt < 4; nt++) {
                int n0 = (no + nt * 8 + gid) * HSTR + tig;
                bh[nt][0] = __float_as_uint(sB_h[n0]);
                bh[nt][1] = __float_as_uint(sB_h[n0 + 4]);
                bl[nt][0] = __float_as_uint(sB_l[n0]);
                bl[nt][1] = __float_as_uint(sB_l[n0 + 4]);
            }
#pragma unroll
            for (int mt = 0; mt < 4; mt++)
#pragma unroll
                for (int nt = 0; nt < 4; nt++) {
                    mma_tf32(c[mt][nt], ah[mt], bh[nt]);
                    mma_tf32(c[mt][nt], ah[mt], bl[nt]);
                }
        }

        if (kt + 1 < nk) {
            sts_a(1 - p, ra0, lrow);
            sts_a(1 - p, ra1, lrow + 64);
            sts_b(1 - p, rb0, lrow);
            sts_b(1 - p, rb1, lrow + 64);
        }
        __syncthreads();
        p ^= 1;
    }

#pragma unroll
    for (int nt = 0; nt < 4; nt++) {
        int col = bx * 128 + no + nt * 8 + tig * 2;
        float bv0 = bias[col], bv1 = bias[col + 1];
#pragma unroll
        for (int mt = 0; mt < 4; mt++) {
            int row0 = by * 128 + mo + mt * 16 + gid;
            float2 v0 = make_float2(c[mt][nt][0] + bv0, c[mt][nt][1] + bv1);
            float2 v1 = make_float2(c[mt][nt][2] + bv0, c[mt][nt][3] + bv1);
            *(float2*)(C + (size_t)row0 * N + col) = v0;
            *(float2*)(C + (size_t)(row0 + 8) * N + col) = v1;
        }
    }
}

// ---------------- grid barrier helpers ---------------------------------------
__device__ __forceinline__ unsigned int ld_acq(const unsigned int* p) {
    unsigned int v;
    asm volatile("ld.acquire.gpu.global.u32 %0, [%1];" : "=r"(v) : "l"(p));
    return v;
}
__device__ __forceinline__ void grid_sync(unsigned int* cnt, unsigned int target) {
    __syncthreads();
    if (threadIdx.x == 0) {
        asm volatile("red.release.gpu.global.add.u32 [%0], %1;" :: "l"(cnt), "r"(1u));
        unsigned int guard = 0;
        while (ld_acq(cnt) < target) {
            __nanosleep(64);
            if (++guard > 30000000u) break;
        }
    }
    __syncthreads();
}

__global__ void reset_sync(unsigned int* p) { p[0] = 0; p[1] = 0; }

// ---------------- persistent bidirectional LSTM recurrence --------------------
// R7 structure verbatim (known-pass) + fused mean: each thread owns (b=lane,
// j=warp-unit, dir) for all t, so it accumulates hsum in a register and writes
// avg once at exit (avg != nullptr only for the layer-1 launch).
__device__ __forceinline__ float sigmoidf(float x) { return 1.f / (1.f + expf(-x)); }

__global__ __launch_bounds__(256) void lstm_persist(
    const float* __restrict__ xg0, const float* __restrict__ xg1,
    const float* __restrict__ Whh0, const float* __restrict__ Whh1,
    float* __restrict__ seq,   // [B*T, 1024]: fwd cols 0..511, bwd 512..1023
    float* __restrict__ avg,   // [B, 1024] or nullptr
    unsigned int* __restrict__ sync_cnt)
{
    extern __shared__ float smem[];
    float* ws = smem;                 // 16384 floats = 64 KB (weights)
    float* hs = smem + 16384;         // 512*33 floats (h staging)

    const int tid  = threadIdx.x;
    const int dir  = blockIdx.y;
    const int b    = tid & 31;
    const int warp = tid >> 5;
    const int jbase = blockIdx.x << 3;
    const int j    = jbase + warp;

    const float* whh = dir ? Whh1 : Whh0;
    for (int i = tid; i < 4096; i += 256) {
        int r  = i >> 7;
        int k4 = i & 127;
        int j_local = r >> 2, gate = r & 3;
        ((float4*)ws)[r * 128 + k4] =
            ((const float4*)(whh + (size_t)(gate * 512 + jbase + j_local) * 512))[k4];
    }

    const float4* wi = (const float4*)(ws + (warp * 4 + 0) * 512);
    const float4* wf = (const float4*)(ws + (warp * 4 + 1) * 512);
    const float4* wg = (const float4*)(ws + (warp * 4 + 2) * 512);
    const float4* wo = (const float4*)(ws + (warp * 4 + 3) * 512);

    const float* xg = dir ? xg1 : xg0;
    const unsigned int nb = gridDim.x * gridDim.y;   // 128
    unsigned int target = 0;
    float c = 0.f;
    float hsum = 0.f;

    // prefetch xg for step 0 (independent of h)
    float pxi, pxf, pxg, pxo;
    {
        int t0 = dir ? (Tlen - 1) : 0;
        int bs = (b * Tlen + t0) * 2048;
        pxi = xg[bs + j];        pxf = xg[bs + 512 + j];
        pxg = xg[bs + 1024 + j]; pxo = xg[bs + 1536 + j];
    }

    for (int s = 0; s < Tlen; ++s) {
        const int tcur = dir ? (Tlen - 1 - s) : s;

        if (s == 0) {
            for (int i = tid; i < 512 * 33; i += 256) hs[i] = 0.f;
        } else {
            const int tprev = dir ? (tcur + 1) : (tcur - 1);
            const int lb  = tid >> 3;
            const int klo = (tid & 7) << 2;
            const float* hp = seq + (size_t)(lb * Tlen + tprev) * 1024 + dir * 512;
#pragma unroll
            for (int it = 0; it < 16; ++it) {
                int k = klo + (it << 5);
                float4 v = *(const float4*)(hp + k);
                hs[(k + 0) * 33 + lb] = v.x;
                hs[(k + 1) * 33 + lb] = v.y;
                hs[(k + 2) * 33 + lb] = v.z;
                hs[(k + 3) * 33 + lb] = v.w;
            }
        }
        __syncthreads();

        // dual accumulators per gate: even k4 -> *, odd k4 -> *b
        float ai = 0.f, af = 0.f, ag = 0.f, ao = 0.f;
        float aib = 0.f, afb = 0.f, agb = 0.f, aob = 0.f;
#pragma unroll 2
        for (int k4 = 0; k4 < 128; k4 += 2) {
            {
                float4 vi = wi[k4], vf = wf[k4], vg = wg[k4], vo = wo[k4];
                int kb = k4 << 2;
                float h0 = hs[(kb + 0) * 33 + b];
                float h1 = hs[(kb + 1) * 33 + b];
                float h2 = hs[(kb + 2) * 33 + b];
                float h3 = hs[(kb + 3) * 33 + b];
                ai += vi.x * h0; ai += vi.y * h1; ai += vi.z * h2; ai += vi.w * h3;
                af += vf.x * h0; af += vf.y * h1; af += vf.z * h2; af += vf.w * h3;
                ag += vg.x * h0; ag += vg.y * h1; ag += vg.z * h2; ag += vg.w * h3;
                ao += vo.x * h0; ao += vo.y * h1; ao += vo.z * h2; ao += vo.w * h3;
            }
            {
                float4 vi = wi[k4 + 1], vf = wf[k4 + 1], vg = wg[k4 + 1], vo = wo[k4 + 1];
                int kb = (k4 + 1) << 2;
                float h0 = hs[(kb + 0) * 33 + b];
                float h1 = hs[(kb + 1) * 33 + b];
                float h2 = hs[(kb + 2) * 33 + b];
                float h3 = hs[(kb + 3) * 33 + b];
                aib += vi.x * h0; aib += vi.y * h1; aib += vi.z * h2; aib += vi.w * h3;
                afb += vf.x * h0; afb += vf.y * h1; afb += vf.z * h2; afb += vf.w * h3;
                agb += vg.x * h0; agb += vg.y * h1; agb += vg.z * h2; agb += vg.w * h3;
                aob += vo.x * h0; aob += vo.y * h1; aob += vo.z * h2; aob += vo.w * h3;
            }
        }

        float gi = (ai + aib) + pxi;
        float gf = (af + afb) + pxf;
        float gg = (ag + agb) + pxg;
        float go = (ao + aob) + pxo;

        c = sigmoidf(gf) * c + sigmoidf(gi) * tanhf(gg);
        float h = sigmoidf(go) * tanhf(c);
        seq[(size_t)(b * Tlen + tcur) * 1024 + dir * 512 + j] = h;
        hsum += h;

        if (s + 1 < Tlen) {
            // prefetch next step's xg before the barrier (hidden by the spin)
            int tn = dir ? (tcur - 1) : (tcur + 1);
            int bs = (b * Tlen + tn) * 2048;
            pxi = xg[bs + j];        pxf = xg[bs + 512 + j];
            pxg = xg[bs + 1024 + j]; pxo = xg[bs + 1536 + j];

            target += nb;
            grid_sync(sync_cnt, target);   // also guards hs overwrite next step
        }
    }

    if (avg) avg[b * 1024 + dir * 512 + j] = hsum * (1.f / Tlen);
}

// ---------------- launch ------------------------------------------------------
extern "C" void kernel_launch(void* const* d_in, const int* in_sizes, int n_in,
                              void* d_out, int out_size)
{
    const float* x     = (const float*)d_in[0];
    const float* Wih0f = (const float*)d_in[1];
    const float* Whh0f = (const float*)d_in[2];
    const float* b0f   = (const float*)d_in[3];
    const float* Wih0b = (const float*)d_in[4];
    const float* Whh0b = (const float*)d_in[5];
    const float* b0b   = (const float*)d_in[6];
    const float* Wih1f = (const float*)d_in[7];
    const float* Whh1f = (const float*)d_in[8];
    const float* b1f   = (const float*)d_in[9];
    const float* Wih1b = (const float*)d_in[10];
    const float* Whh1b = (const float*)d_in[11];
    const float* b1b   = (const float*)d_in[12];

    float* avg    = (float*)d_out;
    float* outseq = avg + Bsz * 2 * Hd;   // avg_out first, then out [B,T,1024]

    float *xg0, *xg1, *x1;
    unsigned int* syncp;
    cudaGetSymbolAddress((void**)&xg0, g_xg0);
    cudaGetSymbolAddress((void**)&xg1, g_xg1);
    cudaGetSymbolAddress((void**)&x1,  g_x1);
    cudaGetSymbolAddress((void**)&syncp, g_sync);

    const int lstm_smem = (16384 + 512 * 33) * sizeof(float);   // 133120 B
    cudaFuncSetAttribute(lstm_persist, cudaFuncAttributeMaxDynamicSharedMemorySize, lstm_smem);
    cudaFuncSetAttribute(tf32_gemm_bias, cudaFuncAttributeMaxDynamicSharedMemorySize, GEMM_SMEM);

    dim3 gemm_grid(2048 / 128, 16384 / 128);     // (16, 128)
    dim3 step_grid(64, 2);

    reset_sync<<<1, 1>>>(syncp);

    // Layer 0 input gates (tensor cores, tf32 2-term split)
    tf32_gemm_bias<<<gemm_grid, 256, GEMM_SMEM>>>(x, Wih0f, b0f, xg0, 16384, 2048, 512);
    tf32_gemm_bias<<<gemm_grid, 256, GEMM_SMEM>>>(x, Wih0b, b0b, xg1, 16384, 2048, 512);
    // Layer 0 recurrence (persistent, grid-sync)
    lstm_persist<<<step_grid, 256, lstm_smem>>>(xg0, xg1, Whh0f, Whh0b, x1, nullptr, syncp);
    // Layer 1 input gates (K = 1024)
    tf32_gemm_bias<<<gemm_grid, 256, GEMM_SMEM>>>(x1, Wih1f, b1f, xg0, 16384, 2048, 1024);
    tf32_gemm_bias<<<gemm_grid, 256, GEMM_SMEM>>>(x1, Wih1b, b1b, xg1, 16384, 2048, 1024);
    // Layer 1 recurrence -> out region of d_out, mean fused
    lstm_persist<<<step_grid, 256, lstm_smem>>>(xg0, xg1, Whh1f, Whh1b, outseq, avg, syncp + 1);
}

// round 10
// speedup vs baseline: 1.3711x; 1.0608x over previous
#include <cuda_runtime.h>
#include <math.h>

#define Bsz 32
#define Tlen 512
#define Hd 512

// ---------------- scratch (static device globals per harness rules) ----------
__device__ float g_xg0[(size_t)Bsz * Tlen * 4 * Hd];   // 134 MB  (dir 0 gates)
__device__ float g_xg1[(size_t)Bsz * Tlen * 4 * Hd];   // 134 MB  (dir 1 gates)
__device__ float g_x1[(size_t)Bsz * Tlen * 2 * Hd];    // 64 MB   (layer-0 output)
__device__ unsigned int g_sync[4];                     // per-layer, per-dir barriers

// ---------------- tf32 helpers ------------------------------------------------
__device__ __forceinline__ float tf32_round(float v) {
    unsigned r;
    asm("cvt.rna.tf32.f32 %0, %1;" : "=r"(r) : "f"(v));
    return __uint_as_float(r);
}
__device__ __forceinline__ void mma_tf32(float* c, const unsigned* a, const unsigned* b) {
    asm volatile(
        "mma.sync.aligned.m16n8k8.row.col.f32.tf32.tf32.f32 "
        "{%0,%1,%2,%3}, {%4,%5,%6,%7}, {%8,%9}, {%0,%1,%2,%3};"
        : "+f"(c[0]), "+f"(c[1]), "+f"(c[2]), "+f"(c[3])
        : "r"(a[0]), "r"(a[1]), "r"(a[2]), "r"(a[3]), "r"(b[0]), "r"(b[1]));
}

// ---------------- TF32 2-term split GEMM: C = A*W^T + bias --------------------
#define HSTR 12
#define TILE_F (2 * 128 * HSTR)
#define BUF_F  (3 * TILE_F)
#define GEMM_SMEM (2 * BUF_F * 4)

__global__ __launch_bounds__(256) void tf32_gemm_bias(
    const float* __restrict__ A, const float* __restrict__ W,
    const float* __restrict__ bias, float* __restrict__ C,
    int M, int N, int K)
{
    extern __shared__ float sm[];
    const int tid  = threadIdx.x;
    const int lane = tid & 31;
    const int warp = tid >> 5;
    const int gid  = lane >> 2;
    const int tig  = lane & 3;
    const int bx = blockIdx.x, by = blockIdx.y;
    const int mo = (warp >> 2) * 64;
    const int no = (warp & 3) * 32;

    const int lrow = tid >> 2;
    const int lkq  = (tid & 3) << 2;
    const int lhalf = lkq >> 3;
    const int lkoff = lkq & 7;

    const float* Ag0 = A + (size_t)(by * 128 + lrow) * K + lkq;
    const float* Ag1 = A + (size_t)(by * 128 + lrow + 64) * K + lkq;
    const float* Wg0 = W + (size_t)(bx * 128 + lrow) * K + lkq;
    const float* Wg1 = W + (size_t)(bx * 128 + lrow + 64) * K + lkq;

    float c[4][4][4];
#pragma unroll
    for (int mt = 0; mt < 4; mt++)
#pragma unroll
        for (int nt = 0; nt < 4; nt++)
#pragma unroll
            for (int i = 0; i < 4; i++) c[mt][nt][i] = 0.f;

    const int nk = K >> 4;
    float4 ra0, ra1, rb0, rb1;

    ra0 = *(const float4*)Ag0; ra1 = *(const float4*)Ag1;
    rb0 = *(const float4*)Wg0; rb1 = *(const float4*)Wg1;

    auto sts_a = [&](int p, float4 v, int row) {
        float* dst = sm + p * BUF_F + lhalf * 1536 + row * HSTR + lkoff;
        float4 hv;
        hv.x = tf32_round(v.x); hv.y = tf32_round(v.y);
        hv.z = tf32_round(v.z); hv.w = tf32_round(v.w);
        *(float4*)dst = hv;
    };
    auto sts_b = [&](int p, float4 v, int row) {
        float* dst_h = sm + p * BUF_F + TILE_F + lhalf * 1536 + row * HSTR + lkoff;
        float4 hv, lv;
        hv.x = tf32_round(v.x); lv.x = tf32_round(v.x - hv.x);
        hv.y = tf32_round(v.y); lv.y = tf32_round(v.y - hv.y);
        hv.z = tf32_round(v.z); lv.z = tf32_round(v.z - hv.z);
        hv.w = tf32_round(v.w); lv.w = tf32_round(v.w - hv.w);
        *(float4*)dst_h = hv;
        *(float4*)(dst_h + TILE_F) = lv;
    };

    sts_a(0, ra0, lrow);
    sts_a(0, ra1, lrow + 64);
    sts_b(0, rb0, lrow);
    sts_b(0, rb1, lrow + 64);
    __syncthreads();

    int p = 0;
    for (int kt = 0; kt < nk; ++kt) {
        if (kt + 1 < nk) {
            const int k0 = (kt + 1) << 4;
            ra0 = *(const float4*)(Ag0 + k0); ra1 = *(const float4*)(Ag1 + k0);
            rb0 = *(const float4*)(Wg0 + k0); rb1 = *(const float4*)(Wg1 + k0);
        }

#pragma unroll
        for (int h = 0; h < 2; ++h) {
            const float* sA_h = sm + p * BUF_F + h * 1536;
            const float* sB_h = sA_h + TILE_F;
            const float* sB_l = sA_h + 2 * TILE_F;

            unsigned ah[4][4], bh[4][2], bl[4][2];
#pragma unroll
            for (int mt = 0; mt < 4; mt++) {
                int r0 = (mo + mt * 16 + gid) * HSTR + tig;
                ah[mt][0] = __float_as_uint(sA_h[r0]);
                ah[mt][1] = __float_as_uint(sA_h[r0 + 8 * HSTR]);
                ah[mt][2] = __float_as_uint(sA_h[r0 + 4]);
                ah[mt][3] = __float_as_uint(sA_h[r0 + 8 * HSTR + 4]);
            }
#pragma unroll
            for (int nt = 0; nt < 4; nt++) {
                int n0 = (no + nt * 8 + gid) * HSTR + tig;
                bh[nt][0] = __float_as_uint(sB_h[n0]);
                bh[nt][1] = __float_as_uint(sB_h[n0 + 4]);
                bl[nt][0] = __float_as_uint(sB_l[n0]);
                bl[nt][1] = __float_as_uint(sB_l[n0 + 4]);
            }
#pragma unroll
            for (int mt = 0; mt < 4; mt++)
#pragma unroll
                for (int nt = 0; nt < 4; nt++) {
                    mma_tf32(c[mt][nt], ah[mt], bh[nt]);
                    mma_tf32(c[mt][nt], ah[mt], bl[nt]);
                }
        }

        if (kt + 1 < nk) {
            sts_a(1 - p, ra0, lrow);
            sts_a(1 - p, ra1, lrow + 64);
            sts_b(1 - p, rb0, lrow);
            sts_b(1 - p, rb1, lrow + 64);
        }
        __syncthreads();
        p ^= 1;
    }

#pragma unroll
    for (int nt = 0; nt < 4; nt++) {
        int col = bx * 128 + no + nt * 8 + tig * 2;
        float bv0 = bias[col], bv1 = bias[col + 1];
#pragma unroll
        for (int mt = 0; mt < 4; mt++) {
            int row0 = by * 128 + mo + mt * 16 + gid;
            float2 v0 = make_float2(c[mt][nt][0] + bv0, c[mt][nt][1] + bv1);
            float2 v1 = make_float2(c[mt][nt][2] + bv0, c[mt][nt][3] + bv1);
            *(float2*)(C + (size_t)row0 * N + col) = v0;
            *(float2*)(C + (size_t)(row0 + 8) * N + col) = v1;
        }
    }
}

// ---------------- grid barrier helpers ---------------------------------------
__device__ __forceinline__ unsigned int ld_acq(const unsigned int* p) {
    unsigned int v;
    asm volatile("ld.acquire.gpu.global.u32 %0, [%1];" : "=r"(v) : "l"(p));
    return v;
}
__device__ __forceinline__ void grid_sync(unsigned int* cnt, unsigned int target) {
    __syncthreads();
    if (threadIdx.x == 0) {
        asm volatile("red.release.gpu.global.add.u32 [%0], %1;" :: "l"(cnt), "r"(1u));
        unsigned int guard = 0;
        while (ld_acq(cnt) < target) {
            __nanosleep(32);
            if (++guard > 30000000u) break;
        }
    }
    __syncthreads();
}

__global__ void reset_sync(unsigned int* p) { p[0] = 0; p[1] = 0; p[2] = 0; p[3] = 0; }

// ---------------- persistent bidirectional LSTM recurrence --------------------
// R9 structure (known-pass). R10 deltas: inner matvec unroll 2 -> 8 (deep LDS
// front-batching; big register headroom at 48 regs), per-DIRECTION barriers
// (64-CTA sync domains; dirs never share data), nanosleep 32.
__device__ __forceinline__ float sigmoidf(float x) { return 1.f / (1.f + expf(-x)); }

__global__ __launch_bounds__(256) void lstm_persist(
    const float* __restrict__ xg0, const float* __restrict__ xg1,
    const float* __restrict__ Whh0, const float* __restrict__ Whh1,
    float* __restrict__ seq,   // [B*T, 1024]: fwd cols 0..511, bwd 512..1023
    float* __restrict__ avg,   // [B, 1024] or nullptr
    unsigned int* __restrict__ sync_base)
{
    extern __shared__ float smem[];
    float* ws = smem;                 // 16384 floats = 64 KB (weights)
    float* hs = smem + 16384;         // 512*33 floats (h staging)

    const int tid  = threadIdx.x;
    const int dir  = blockIdx.y;
    const int b    = tid & 31;
    const int warp = tid >> 5;
    const int jbase = blockIdx.x << 3;
    const int j    = jbase + warp;
    unsigned int* sync_cnt = sync_base + dir;   // per-direction barrier

    const float* whh = dir ? Whh1 : Whh0;
    for (int i = tid; i < 4096; i += 256) {
        int r  = i >> 7;
        int k4 = i & 127;
        int j_local = r >> 2, gate = r & 3;
        ((float4*)ws)[r * 128 + k4] =
            ((const float4*)(whh + (size_t)(gate * 512 + jbase + j_local) * 512))[k4];
    }

    const float4* wi = (const float4*)(ws + (warp * 4 + 0) * 512);
    const float4* wf = (const float4*)(ws + (warp * 4 + 1) * 512);
    const float4* wg = (const float4*)(ws + (warp * 4 + 2) * 512);
    const float4* wo = (const float4*)(ws + (warp * 4 + 3) * 512);

    const float* xg = dir ? xg1 : xg0;
    const unsigned int nb = gridDim.x;          // 64 CTAs per direction
    unsigned int target = 0;
    float c = 0.f;
    float hsum = 0.f;

    // prefetch xg for step 0 (independent of h)
    float pxi, pxf, pxg, pxo;
    {
        int t0 = dir ? (Tlen - 1) : 0;
        int bs = (b * Tlen + t0) * 2048;
        pxi = xg[bs + j];        pxf = xg[bs + 512 + j];
        pxg = xg[bs + 1024 + j]; pxo = xg[bs + 1536 + j];
    }

    for (int s = 0; s < Tlen; ++s) {
        const int tcur = dir ? (Tlen - 1 - s) : s;

        if (s == 0) {
            for (int i = tid; i < 512 * 33; i += 256) hs[i] = 0.f;
        } else {
            const int tprev = dir ? (tcur + 1) : (tcur - 1);
            const int lb  = tid >> 3;
            const int klo = (tid & 7) << 2;
            const float* hp = seq + (size_t)(lb * Tlen + tprev) * 1024 + dir * 512;
#pragma unroll
            for (int it = 0; it < 16; ++it) {
                int k = klo + (it << 5);
                float4 v = *(const float4*)(hp + k);
                hs[(k + 0) * 33 + lb] = v.x;
                hs[(k + 1) * 33 + lb] = v.y;
                hs[(k + 2) * 33 + lb] = v.z;
                hs[(k + 3) * 33 + lb] = v.w;
            }
        }
        __syncthreads();

        // dual accumulators per gate; deep unroll for LDS front-batching
        float ai = 0.f, af = 0.f, ag = 0.f, ao = 0.f;
        float aib = 0.f, afb = 0.f, agb = 0.f, aob = 0.f;
#pragma unroll 4
        for (int k4 = 0; k4 < 128; k4 += 2) {
            {
                float4 vi = wi[k4], vf = wf[k4], vg = wg[k4], vo = wo[k4];
                int kb = k4 << 2;
                float h0 = hs[(kb + 0) * 33 + b];
                float h1 = hs[(kb + 1) * 33 + b];
                float h2 = hs[(kb + 2) * 33 + b];
                float h3 = hs[(kb + 3) * 33 + b];
                ai += vi.x * h0; ai += vi.y * h1; ai += vi.z * h2; ai += vi.w * h3;
                af += vf.x * h0; af += vf.y * h1; af += vf.z * h2; af += vf.w * h3;
                ag += vg.x * h0; ag += vg.y * h1; ag += vg.z * h2; ag += vg.w * h3;
                ao += vo.x * h0; ao += vo.y * h1; ao += vo.z * h2; ao += vo.w * h3;
            }
            {
                float4 vi = wi[k4 + 1], vf = wf[k4 + 1], vg = wg[k4 + 1], vo = wo[k4 + 1];
                int kb = (k4 + 1) << 2;
                float h0 = hs[(kb + 0) * 33 + b];
                float h1 = hs[(kb + 1) * 33 + b];
                float h2 = hs[(kb + 2) * 33 + b];
                float h3 = hs[(kb + 3) * 33 + b];
                aib += vi.x * h0; aib += vi.y * h1; aib += vi.z * h2; aib += vi.w * h3;
                afb += vf.x * h0; afb += vf.y * h1; afb += vf.z * h2; afb += vf.w * h3;
                agb += vg.x * h0; agb += vg.y * h1; agb += vg.z * h2; agb += vg.w * h3;
                aob += vo.x * h0; aob += vo.y * h1; aob += vo.z * h2; aob += vo.w * h3;
            }
        }

        float gi = (ai + aib) + pxi;
        float gf = (af + afb) + pxf;
        float gg = (ag + agb) + pxg;
        float go = (ao + aob) + pxo;

        c = sigmoidf(gf) * c + sigmoidf(gi) * tanhf(gg);
        float h = sigmoidf(go) * tanhf(c);
        seq[(size_t)(b * Tlen + tcur) * 1024 + dir * 512 + j] = h;
        hsum += h;

        if (s + 1 < Tlen) {
            // prefetch next step's xg before the barrier (hidden by the spin)
            int tn = dir ? (tcur - 1) : (tcur + 1);
            int bs = (b * Tlen + tn) * 2048;
            pxi = xg[bs + j];        pxf = xg[bs + 512 + j];
            pxg = xg[bs + 1024 + j]; pxo = xg[bs + 1536 + j];

            target += nb;
            grid_sync(sync_cnt, target);   // also guards hs overwrite next step
        }
    }

    if (avg) avg[b * 1024 + dir * 512 + j] = hsum * (1.f / Tlen);
}

// ---------------- launch ------------------------------------------------------
extern "C" void kernel_launch(void* const* d_in, const int* in_sizes, int n_in,
                              void* d_out, int out_size)
{
    const float* x     = (const float*)d_in[0];
    const float* Wih0f = (const float*)d_in[1];
    const float* Whh0f = (const float*)d_in[2];
    const float* b0f   = (const float*)d_in[3];
    const float* Wih0b = (const float*)d_in[4];
    const float* Whh0b = (const float*)d_in[5];
    const float* b0b   = (const float*)d_in[6];
    const float* Wih1f = (const float*)d_in[7];
    const float* Whh1f = (const float*)d_in[8];
    const float* b1f   = (const float*)d_in[9];
    const float* Wih1b = (const float*)d_in[10];
    const float* Whh1b = (const float*)d_in[11];
    const float* b1b   = (const float*)d_in[12];

    float* avg    = (float*)d_out;
    float* outseq = avg + Bsz * 2 * Hd;   // avg_out first, then out [B,T,1024]

    float *xg0, *xg1, *x1;
    unsigned int* syncp;
    cudaGetSymbolAddress((void**)&xg0, g_xg0);
    cudaGetSymbolAddress((void**)&xg1, g_xg1);
    cudaGetSymbolAddress((void**)&x1,  g_x1);
    cudaGetSymbolAddress((void**)&syncp, g_sync);

    const int lstm_smem = (16384 + 512 * 33) * sizeof(float);   // 133120 B
    cudaFuncSetAttribute(lstm_persist, cudaFuncAttributeMaxDynamicSharedMemorySize, lstm_smem);
    cudaFuncSetAttribute(tf32_gemm_bias, cudaFuncAttributeMaxDynamicSharedMemorySize, GEMM_SMEM);

    dim3 gemm_grid(2048 / 128, 16384 / 128);     // (16, 128)
    dim3 step_grid(64, 2);

    reset_sync<<<1, 1>>>(syncp);

    // Layer 0 input gates (tensor cores, tf32 2-term split)
    tf32_gemm_bias<<<gemm_grid, 256, GEMM_SMEM>>>(x, Wih0f, b0f, xg0, 16384, 2048, 512);
    tf32_gemm_bias<<<gemm_grid, 256, GEMM_SMEM>>>(x, Wih0b, b0b, xg1, 16384, 2048, 512);
    // Layer 0 recurrence (persistent, per-dir grid-sync: counters 0,1)
    lstm_persist<<<step_grid, 256, lstm_smem>>>(xg0, xg1, Whh0f, Whh0b, x1, nullptr, syncp);
    // Layer 1 input gates (K = 1024)
    tf32_gemm_bias<<<gemm_grid, 256, GEMM_SMEM>>>(x1, Wih1f, b1f, xg0, 16384, 2048, 1024);
    tf32_gemm_bias<<<gemm_grid, 256, GEMM_SMEM>>>(x1, Wih1b, b1b, xg1, 16384, 2048, 1024);
    // Layer 1 recurrence -> out region of d_out, mean fused (counters 2,3)
    lstm_persist<<<step_grid, 256, lstm_smem>>>(xg0, xg1, Whh1f, Whh1b, outseq, avg, syncp + 2);
}